// round 11
// baseline (speedup 1.0000x reference)
#include <cuda_runtime.h>
#include <cuda_bf16.h>
#include <cstdint>

#define BN 2
#define BT 2048
#define BE 1024
#define BH 16
#define DH 64

// ---- packed f32x2 helpers (sm_103a 2x fp32) --------------------------------
#define FMA2(d, a, b) asm("fma.rn.f32x2 %0, %1, %2, %0;" : "+l"(d) : "l"(a), "l"(b))
#define MUL2(d, a, b) asm("mul.rn.f32x2 %0, %1, %2;" : "=l"(d) : "l"(a), "l"(b))
#define ADD2(d, a, b) asm("add.rn.f32x2 %0, %1, %2;" : "=l"(d) : "l"(a), "l"(b))
#define DUP2(out, x) do { unsigned __du = __float_as_uint(x); \
    asm("mov.b64 %0, {%1, %1};" : "=l"(out) : "r"(__du)); } while (0)
#define UNPK2(lo, hi, p) asm("mov.b64 {%0, %1}, %2;" : "=r"(lo), "=r"(hi) : "l"(p))

// ---- warp-level tf32 MMA (sm_80+ encoding; runs on Blackwell tensor cores) --
__device__ __forceinline__ void mma_tf32(float* d, const uint32_t* a,
                                         const uint32_t* b) {
    asm("mma.sync.aligned.m16n8k8.row.col.f32.tf32.tf32.f32 "
        "{%0,%1,%2,%3}, {%4,%5,%6,%7}, {%8,%9}, {%0,%1,%2,%3};"
        : "+f"(d[0]), "+f"(d[1]), "+f"(d[2]), "+f"(d[3])
        : "r"(a[0]), "r"(a[1]), "r"(a[2]), "r"(a[3]), "r"(b[0]), "r"(b[1]));
}

__device__ __forceinline__ float tf32_hi(float x) {
    return __uint_as_float(__float_as_uint(x) & 0xFFFFE000u);
}

// Scratch (allocation-free rule: __device__ globals)
__device__ float g_Q[(size_t)BN * BH * BT * DH]; // [n,h,t,d]
__device__ float g_K[(size_t)BN * BH * BT * DH];
__device__ float g_V[(size_t)BN * BH * BT * DH];
__device__ float g_C[(size_t)BN * BT * BH * DH]; // concat layout [n,t,h,d]

#define PITCH 20   // 16 k-floats + pad: (20*r + c) % 32 covers all banks

// ---------------------------------------------------------------------------
// Projection via mma.sync tf32 (3x split): Out[n,h,t,d] = sum_e X[t,e]*W[e,d]
// Block: 128t x 64d tile, 256 thr = 8 warps (4M x 2N), warp tile 32x32.
// ---------------------------------------------------------------------------
__global__ __launch_bounds__(256) void proj_mma(
    const float* __restrict__ qin, const float* __restrict__ kin,
    const float* __restrict__ vin,
    const float* __restrict__ Wq, const float* __restrict__ Wk,
    const float* __restrict__ Wv)
{
    __shared__ float XsHi[128 * PITCH], XsLo[128 * PITCH];
    __shared__ float WsHi[64 * PITCH],  WsLo[64 * PITCH];

    int tid = threadIdx.x;
    int warp = tid >> 5, lane = tid & 31;
    int wm = warp >> 1, wn = warp & 1;
    int g = lane >> 2, tg = lane & 3;

    int z = blockIdx.z, nh = blockIdx.y, t0 = blockIdx.x * 128, n = nh >> 4;
    const float* X = (z == 0 ? qin : z == 1 ? kin : vin)
                     + (size_t)n * BT * BE + (size_t)t0 * BE;
    const float* W = (z == 0 ? Wq : z == 1 ? Wk : Wv)
                     + (size_t)(nh & 15) * BE * DH;
    float* O = (z == 0 ? g_Q : z == 1 ? g_K : g_V) + ((size_t)nh * BT + t0) * DH;

    float acc[2][4][4];
#pragma unroll
    for (int mt = 0; mt < 2; ++mt)
#pragma unroll
        for (int nt = 0; nt < 4; ++nt)
#pragma unroll
            for (int j = 0; j < 4; ++j) acc[mt][nt][j] = 0.f;

    for (int e0 = 0; e0 < BE; e0 += 16) {
        // X tile: 128 x 16 (512 float4, 2/thread), split hi/lo
#pragma unroll
        for (int i = 0; i < 2; ++i) {
            int f = tid + i * 256;
            int row = f >> 2, c4 = f & 3;
            float4 v = *reinterpret_cast<const float4*>(
                X + (size_t)row * BE + e0 + c4 * 4);
            float4 hi, lo;
            hi.x = tf32_hi(v.x); lo.x = v.x - hi.x;
            hi.y = tf32_hi(v.y); lo.y = v.y - hi.y;
            hi.z = tf32_hi(v.z); lo.z = v.z - hi.z;
            hi.w = tf32_hi(v.w); lo.w = v.w - hi.w;
            *reinterpret_cast<float4*>(&XsHi[row * PITCH + c4 * 4]) = hi;
            *reinterpret_cast<float4*>(&XsLo[row * PITCH + c4 * 4]) = lo;
        }
        // W tile: W[e][d] -> Ws[d][k] transpose (256 float4 over d, 1/thread)
        {
            int e = tid >> 4, d4 = tid & 15;
            float4 v = *reinterpret_cast<const float4*>(
                W + (size_t)(e0 + e) * DH + d4 * 4);
            float vv[4] = {v.x, v.y, v.z, v.w};
#pragma unroll
            for (int j = 0; j < 4; ++j) {
                int d = d4 * 4 + j;
                float h = tf32_hi(vv[j]);
                WsHi[d * PITCH + e] = h;
                WsLo[d * PITCH + e] = vv[j] - h;
            }
        }
        __syncthreads();

#pragma unroll
        for (int k8 = 0; k8 < 2; ++k8) {
            int kb = k8 * 8;
            uint32_t bh[4][2], bl[4][2];
#pragma unroll
            for (int nt = 0; nt < 4; ++nt) {
                int nn = (wn * 32 + nt * 8 + g) * PITCH + kb;
                bh[nt][0] = __float_as_uint(WsHi[nn + tg]);
                bh[nt][1] = __float_as_uint(WsHi[nn + tg + 4]);
                bl[nt][0] = __float_as_uint(WsLo[nn + tg]);
                bl[nt][1] = __float_as_uint(WsLo[nn + tg + 4]);
            }
#pragma unroll
            for (int mt = 0; mt < 2; ++mt) {
                int r0 = wm * 32 + mt * 16 + g;
                uint32_t ah[4], al[4];
                ah[0] = __float_as_uint(XsHi[r0 * PITCH + kb + tg]);
                ah[1] = __float_as_uint(XsHi[(r0 + 8) * PITCH + kb + tg]);
                ah[2] = __float_as_uint(XsHi[r0 * PITCH + kb + tg + 4]);
                ah[3] = __float_as_uint(XsHi[(r0 + 8) * PITCH + kb + tg + 4]);
                al[0] = __float_as_uint(XsLo[r0 * PITCH + kb + tg]);
                al[1] = __float_as_uint(XsLo[(r0 + 8) * PITCH + kb + tg]);
                al[2] = __float_as_uint(XsLo[r0 * PITCH + kb + tg + 4]);
                al[3] = __float_as_uint(XsLo[(r0 + 8) * PITCH + kb + tg + 4]);
#pragma unroll
                for (int nt = 0; nt < 4; ++nt) {
                    mma_tf32(acc[mt][nt], ah, bh[nt]);
                    mma_tf32(acc[mt][nt], ah, bl[nt]);
                    mma_tf32(acc[mt][nt], al, bh[nt]);
                }
            }
        }
        __syncthreads();
    }

#pragma unroll
    for (int mt = 0; mt < 2; ++mt) {
#pragma unroll
        for (int nt = 0; nt < 4; ++nt) {
            int row = wm * 32 + mt * 16 + g;
            int col = wn * 32 + nt * 8 + tg * 2;
            *reinterpret_cast<float2*>(&O[(size_t)row * DH + col]) =
                make_float2(acc[mt][nt][0], acc[mt][nt][1]);
            *reinterpret_cast<float2*>(&O[(size_t)(row + 8) * DH + col]) =
                make_float2(acc[mt][nt][2], acc[mt][nt][3]);
        }
    }
}

// ---------------------------------------------------------------------------
// Output projection via mma.sync tf32: out[r,c] = sum_k C[r,k]*Wo[c,k] + bo[c]
// Block: 128r x 64c, same warp structure. Wo is naturally K-major (no transpose).
// ---------------------------------------------------------------------------
__global__ __launch_bounds__(256) void outproj_mma(
    const float* __restrict__ Wo, const float* __restrict__ bo,
    float* __restrict__ out)
{
    __shared__ float AsHi[128 * PITCH], AsLo[128 * PITCH];
    __shared__ float BsHi[64 * PITCH],  BsLo[64 * PITCH];

    int tid = threadIdx.x;
    int warp = tid >> 5, lane = tid & 31;
    int wm = warp >> 1, wn = warp & 1;
    int g = lane >> 2, tg = lane & 3;

    int r0b = blockIdx.x * 128, c0b = blockIdx.y * 64;

    float acc[2][4][4];
#pragma unroll
    for (int mt = 0; mt < 2; ++mt)
#pragma unroll
        for (int nt = 0; nt < 4; ++nt)
#pragma unroll
            for (int j = 0; j < 4; ++j) acc[mt][nt][j] = 0.f;

    for (int k0 = 0; k0 < BE; k0 += 16) {
#pragma unroll
        for (int i = 0; i < 2; ++i) {
            int f = tid + i * 256;
            int row = f >> 2, c4 = f & 3;
            float4 v = *reinterpret_cast<const float4*>(
                g_C + (size_t)(r0b + row) * BE + k0 + c4 * 4);
            float4 hi, lo;
            hi.x = tf32_hi(v.x); lo.x = v.x - hi.x;
            hi.y = tf32_hi(v.y); lo.y = v.y - hi.y;
            hi.z = tf32_hi(v.z); lo.z = v.z - hi.z;
            hi.w = tf32_hi(v.w); lo.w = v.w - hi.w;
            *reinterpret_cast<float4*>(&AsHi[row * PITCH + c4 * 4]) = hi;
            *reinterpret_cast<float4*>(&AsLo[row * PITCH + c4 * 4]) = lo;
        }
        {
            int nrow = tid >> 2, c4 = tid & 3;   // 64 rows x 4 float4
            float4 v = *reinterpret_cast<const float4*>(
                Wo + (size_t)(c0b + nrow) * BE + k0 + c4 * 4);
            float4 hi, lo;
            hi.x = tf32_hi(v.x); lo.x = v.x - hi.x;
            hi.y = tf32_hi(v.y); lo.y = v.y - hi.y;
            hi.z = tf32_hi(v.z); lo.z = v.z - hi.z;
            hi.w = tf32_hi(v.w); lo.w = v.w - hi.w;
            *reinterpret_cast<float4*>(&BsHi[nrow * PITCH + c4 * 4]) = hi;
            *reinterpret_cast<float4*>(&BsLo[nrow * PITCH + c4 * 4]) = lo;
        }
        __syncthreads();

#pragma unroll
        for (int k8 = 0; k8 < 2; ++k8) {
            int kb = k8 * 8;
            uint32_t bh[4][2], bl[4][2];
#pragma unroll
            for (int nt = 0; nt < 4; ++nt) {
                int nn = (wn * 32 + nt * 8 + g) * PITCH + kb;
                bh[nt][0] = __float_as_uint(BsHi[nn + tg]);
                bh[nt][1] = __float_as_uint(BsHi[nn + tg + 4]);
                bl[nt][0] = __float_as_uint(BsLo[nn + tg]);
                bl[nt][1] = __float_as_uint(BsLo[nn + tg + 4]);
            }
#pragma unroll
            for (int mt = 0; mt < 2; ++mt) {
                int r0 = wm * 32 + mt * 16 + g;
                uint32_t ah[4], al[4];
                ah[0] = __float_as_uint(AsHi[r0 * PITCH + kb + tg]);
                ah[1] = __float_as_uint(AsHi[(r0 + 8) * PITCH + kb + tg]);
                ah[2] = __float_as_uint(AsHi[r0 * PITCH + kb + tg + 4]);
                ah[3] = __float_as_uint(AsHi[(r0 + 8) * PITCH + kb + tg + 4]);
                al[0] = __float_as_uint(AsLo[r0 * PITCH + kb + tg]);
                al[1] = __float_as_uint(AsLo[(r0 + 8) * PITCH + kb + tg]);
                al[2] = __float_as_uint(AsLo[r0 * PITCH + kb + tg + 4]);
                al[3] = __float_as_uint(AsLo[(r0 + 8) * PITCH + kb + tg + 4]);
#pragma unroll
                for (int nt = 0; nt < 4; ++nt) {
                    mma_tf32(acc[mt][nt], ah, bh[nt]);
                    mma_tf32(acc[mt][nt], ah, bl[nt]);
                    mma_tf32(acc[mt][nt], al, bh[nt]);
                }
            }
        }
        __syncthreads();
    }

#pragma unroll
    for (int mt = 0; mt < 2; ++mt) {
#pragma unroll
        for (int nt = 0; nt < 4; ++nt) {
            int row = r0b + wm * 32 + mt * 16 + g;
            int col = c0b + wn * 32 + nt * 8 + tg * 2;
            float b0 = bo[col], b1 = bo[col + 1];
            *reinterpret_cast<float2*>(&out[(size_t)row * BE + col]) =
                make_float2(acc[mt][nt][0] + b0, acc[mt][nt][1] + b1);
            *reinterpret_cast<float2*>(&out[(size_t)(row + 8) * BE + col]) =
                make_float2(acc[mt][nt][2] + b0, acc[mt][nt][3] + b1);
        }
    }
}

// ---------------------------------------------------------------------------
// Flash attention (causal), f32x2 — unchanged from R3 (measured good).
// ---------------------------------------------------------------------------
__global__ __launch_bounds__(256) void flash_kernel()
{
    int qt = (BT / 64 - 1) - blockIdx.x;
    int nh = blockIdx.y;
    int n = nh >> 4, h = nh & 15;
    int tid = threadIdx.x;
    int row = tid >> 2, seg = tid & 3;
    int row_g = qt * 64 + row;

    const float* Qb = g_Q + ((size_t)nh * BT + (size_t)qt * 64) * DH;
    const float* Kb = g_K + (size_t)nh * BT * DH;
    const float* Vb = g_V + (size_t)nh * BT * DH;

    __shared__ __align__(16) float Ks[64][68];
    __shared__ __align__(16) float Vs[64][68];

    unsigned long long q2[32], o2[32];
    {
        const ulonglong2* qp =
            reinterpret_cast<const ulonglong2*>(Qb + (size_t)row * DH);
        unsigned long long sc2; DUP2(sc2, 0.125f);
#pragma unroll
        for (int j = 0; j < 16; ++j) {
            ulonglong2 t = qp[j];
            MUL2(q2[2 * j], t.x, sc2);
            MUL2(q2[2 * j + 1], t.y, sc2);
        }
    }
#pragma unroll
    for (int j = 0; j < 32; ++j) o2[j] = 0ULL;
    float m = -1e30f, l = 0.f;

    for (int kt = 0; kt <= qt; ++kt) {
        const float4* ksrc =
            reinterpret_cast<const float4*>(Kb + (size_t)kt * 64 * DH);
        const float4* vsrc =
            reinterpret_cast<const float4*>(Vb + (size_t)kt * 64 * DH);
#pragma unroll
        for (int it = 0; it < 4; ++it) {
            int li = tid + it * 256;
            int c = li & 15, r = li >> 4;
            float4 kv = ksrc[r * 16 + c];
            float4 vv = vsrc[r * 16 + c];
            *reinterpret_cast<float4*>(&Ks[r][c * 4]) = kv;
            *reinterpret_cast<float4*>(&Vs[r][c * 4]) = vv;
        }
        __syncthreads();

        float s[16];
#pragma unroll
        for (int i = 0; i < 16; ++i) {
            int key = 4 * i + seg;
            const ulonglong2* kp =
                reinterpret_cast<const ulonglong2*>(&Ks[key][0]);
            ulonglong2 t0 = kp[0];
            unsigned long long s2a, s2b;
            MUL2(s2a, q2[0], t0.x);
            MUL2(s2b, q2[1], t0.y);
#pragma unroll
            for (int j2 = 1; j2 < 16; ++j2) {
                ulonglong2 t = kp[j2];
                FMA2(s2a, q2[2 * j2], t.x);
                FMA2(s2b, q2[2 * j2 + 1], t.y);
            }
            ADD2(s2a, s2a, s2b);
            unsigned lo, hi; UNPK2(lo, hi, s2a);
            s[i] = __uint_as_float(lo) + __uint_as_float(hi);
        }
        if (kt == qt) {
#pragma unroll
            for (int i = 0; i < 16; ++i)
                if (kt * 64 + 4 * i + seg > row_g) s[i] = -1e30f;
        }

        float cmax = s[0];
#pragma unroll
        for (int i = 1; i < 16; ++i) cmax = fmaxf(cmax, s[i]);
        cmax = fmaxf(cmax, __shfl_xor_sync(0xffffffffu, cmax, 1));
        cmax = fmaxf(cmax, __shfl_xor_sync(0xffffffffu, cmax, 2));
        float mt = fmaxf(m, cmax);
        float corr = __expf(m - mt);
        float pown[16];
        float psum = 0.f;
#pragma unroll
        for (int i = 0; i < 16; ++i) {
            pown[i] = __expf(s[i] - mt);
            psum += pown[i];
        }
        psum += __shfl_xor_sync(0xffffffffu, psum, 1);
        psum += __shfl_xor_sync(0xffffffffu, psum, 2);
        l = l * corr + psum;
        m = mt;

        unsigned long long c2; DUP2(c2, corr);
#pragma unroll
        for (int j = 0; j < 32; ++j) MUL2(o2[j], o2[j], c2);

#pragma unroll
        for (int i = 0; i < 16; ++i) {
            int key = 4 * i + seg;
            unsigned long long p2; DUP2(p2, pown[i]);
            const ulonglong2* vp =
                reinterpret_cast<const ulonglong2*>(&Vs[key][0]);
#pragma unroll
            for (int j2 = 0; j2 < 16; ++j2) {
                ulonglong2 t = vp[j2];
                FMA2(o2[2 * j2], p2, t.x);
                FMA2(o2[2 * j2 + 1], p2, t.y);
            }
        }
        __syncthreads();
    }

#pragma unroll
    for (int j = 0; j < 32; ++j) {
        unsigned long long t = __shfl_xor_sync(0xffffffffu, o2[j], 1);
        ADD2(o2[j], o2[j], t);
        t = __shfl_xor_sync(0xffffffffu, o2[j], 2);
        ADD2(o2[j], o2[j], t);
    }
    unsigned long long inv2; DUP2(inv2, 1.0f / l);
#pragma unroll
    for (int j = 0; j < 32; ++j) MUL2(o2[j], o2[j], inv2);

    ulonglong2* dst = reinterpret_cast<ulonglong2*>(
        g_C + (((size_t)n * BT + (size_t)qt * 64 + row) * BH + h) * DH);
#define STORE_SEG(S) \
    { ulonglong2 v; \
      v.x = o2[S * 8 + 0]; v.y = o2[S * 8 + 1]; dst[S * 4 + 0] = v; \
      v.x = o2[S * 8 + 2]; v.y = o2[S * 8 + 3]; dst[S * 4 + 1] = v; \
      v.x = o2[S * 8 + 4]; v.y = o2[S * 8 + 5]; dst[S * 4 + 2] = v; \
      v.x = o2[S * 8 + 6]; v.y = o2[S * 8 + 7]; dst[S * 4 + 3] = v; }
    switch (seg) {
        case 0: STORE_SEG(0); break;
        case 1: STORE_SEG(1); break;
        case 2: STORE_SEG(2); break;
        default: STORE_SEG(3); break;
    }
#undef STORE_SEG
}

// ---------------------------------------------------------------------------
extern "C" void kernel_launch(void* const* d_in, const int* in_sizes, int n_in,
                              void* d_out, int out_size)
{
    const float* q  = (const float*)d_in[0];
    const float* k  = (const float*)d_in[1];
    const float* v  = (const float*)d_in[2];
    // d_in[3] = mask (int32 tril) — causality implemented structurally
    const float* Wq = (const float*)d_in[4];
    const float* Wk = (const float*)d_in[5];
    const float* Wv = (const float*)d_in[6];
    const float* Wo = (const float*)d_in[7];
    const float* bo = (const float*)d_in[8];
    float* out = (float*)d_out;

    proj_mma<<<dim3(BT / 128, BN * BH, 3), 256>>>(q, k, v, Wq, Wk, Wv);
    flash_kernel<<<dim3(BT / 64, BN * BH), 256>>>();
    outproj_mma<<<dim3(BN * BT / 128, BE / 64), 256>>>(Wo, bo, out);
}